// round 9
// baseline (speedup 1.0000x reference)
#include <cuda_runtime.h>
#include <math.h>
#include <stdint.h>

// Problem constants
#define Bb 8
#define Tt 288
#define Nn 2000
#define FLf 145      // T/2+1
#define Ee 128
#define IDd 16
#define Dd 144       // E+ID
#define Hh 128
#define Kk 20

// ---------------- scratch (device globals; no allocation allowed) ----------------
__device__ __align__(16) float g_xf[Bb * Nn * FLf];   // |rfft|  [B,N,FL]
__device__ __align__(16) float g_A[Bb * FLf];         // node-dim norms
__device__ __align__(16) float g_xk[Bb * Nn * Dd];    // concat(xe, nodes)
__device__ __align__(16) float g_x1[Bb * Nn * Hh];    // relu(bmm)
__device__ __align__(16) float g_adp[Bb * Nn * Hh];   // LN-affine @ Wxabs
__device__ float g_mu[Bb];
__device__ float g_rstd[Bb];

// ---------------- K1: DFT magnitude  xf[b,n,f] = |rfft(x[b,:,n,0])[f]| ------------
__global__ __launch_bounds__(160) void k_fft(const float* __restrict__ x) {
    __shared__ float row[Tt];
    __shared__ float twc[Tt];
    __shared__ float tws[Tt];
    int bn = blockIdx.x;
    int b = bn / Nn, n = bn % Nn;
    int tid = threadIdx.x;
    for (int t = tid; t < Tt; t += 160) {
        row[t] = x[(b * Tt + t) * Nn + n];
        float ang = (float)t * (6.2831853071795864769f / (float)Tt);
        float s, c;
        sincosf(ang, &s, &c);
        twc[t] = c;
        tws[t] = s;
    }
    __syncthreads();
    int f = tid;
    if (f < FLf) {
        float re = 0.f, im = 0.f;
        int ph = 0;  // (f*t) mod T, exact integer reduction
        #pragma unroll 4
        for (int t = 0; t < Tt; ++t) {
            float v = row[t];
            re = fmaf(v, twc[ph], re);
            im = fmaf(v, tws[ph], im);
            ph += f;
            if (ph >= Tt) ph -= Tt;
        }
        g_xf[bn * FLf + f] = sqrtf(re * re + im * im);
    }
}

// ---------------- K2: norms over node dim: A[b,f] = max(||xf[b,:,f]||, eps) -------
__global__ __launch_bounds__(256) void k_colnorm() {
    int b = blockIdx.x / FLf, f = blockIdx.x % FLf;
    int tid = threadIdx.x;
    double s = 0.0;
    for (int n = tid; n < Nn; n += 256) {
        float v = g_xf[(b * Nn + n) * FLf + f];
        s += (double)v * (double)v;
    }
    __shared__ double red[256];
    red[tid] = s;
    __syncthreads();
    for (int o = 128; o; o >>= 1) {
        if (tid < o) red[tid] += red[tid + o];
        __syncthreads();
    }
    if (tid == 0) g_A[b * FLf + f] = fmaxf((float)sqrt(red[0]), 1e-12f);
}

// ---- K3: freq-dim normalize + xe = xf2 @ Ex, write xk = [xe | nodes] -------------
__global__ __launch_bounds__(256) void k_embed(const float* __restrict__ Ex,
                                               const float* __restrict__ nodes) {
    __shared__ float v[FLf];
    __shared__ double red[256];
    int bn = blockIdx.x;
    int b = bn / Nn, n = bn % Nn;
    int tid = threadIdx.x;
    double s = 0.0;
    if (tid < FLf) {
        float val = g_xf[bn * FLf + tid] / g_A[b * FLf + tid];
        v[tid] = val;
        s = (double)val * (double)val;
    }
    red[tid] = s;
    __syncthreads();
    for (int o = 128; o; o >>= 1) {
        if (tid < o) red[tid] += red[tid + o];
        __syncthreads();
    }
    float inv = 1.0f / fmaxf((float)sqrt(red[0]), 1e-12f);
    if (tid < Ee) {
        float acc = 0.f;
        #pragma unroll 5
        for (int f = 0; f < FLf; ++f) acc = fmaf(v[f], Ex[f * Ee + tid], acc);
        g_xk[bn * Dd + tid] = acc * inv;  // (v/s)@Ex == (v@Ex)/s
    } else if (tid < Ee + IDd) {
        g_xk[bn * Dd + tid] = nodes[n * IDd + (tid - Ee)];
    }
}

// ---------------- K4: x1[b,n,:] = relu(xk[b,n,:] @ Wd[n])  (Wd read once) ---------
__global__ __launch_bounds__(128) void k_x1(const float* __restrict__ Wd) {
    __shared__ float xs[Bb][Dd];
    int n = blockIdx.x, tid = threadIdx.x;
    for (int i = tid; i < Bb * Dd; i += 128) {
        int b = i / Dd, d = i % Dd;
        xs[b][d] = g_xk[(b * Nn + n) * Dd + d];
    }
    __syncthreads();
    float acc[Bb];
    #pragma unroll
    for (int b = 0; b < Bb; ++b) acc[b] = 0.f;
    const float* W = Wd + (size_t)n * Dd * Hh + tid;
    for (int d = 0; d < Dd; ++d) {
        float w = W[d * Hh];
        #pragma unroll
        for (int b = 0; b < Bb; ++b) acc[b] = fmaf(xs[b][d], w, acc[b]);
    }
    #pragma unroll
    for (int b = 0; b < Bb; ++b)
        g_x1[(b * Nn + n) * Hh + tid] = fmaxf(acc[b], 0.f);
}

// ---------------- K5: LayerNorm stats per batch (fp64 accumulation) ---------------
__global__ __launch_bounds__(256) void k_lnstats() {
    int b = blockIdx.x, tid = threadIdx.x;
    double s = 0.0, s2 = 0.0;
    const float* p = g_x1 + (size_t)b * Nn * Hh;
    for (int i = tid; i < Nn * Hh; i += 256) {
        double v = (double)p[i];
        s += v;
        s2 += v * v;
    }
    __shared__ double r1[256];
    __shared__ double r2[256];
    r1[tid] = s;
    r2[tid] = s2;
    __syncthreads();
    for (int o = 128; o; o >>= 1) {
        if (tid < o) { r1[tid] += r1[tid + o]; r2[tid] += r2[tid + o]; }
        __syncthreads();
    }
    if (tid == 0) {
        double cnt = (double)(Nn * Hh);
        double mu = r1[0] / cnt;
        double var = r2[0] / cnt - mu * mu;
        g_mu[b] = (float)mu;
        g_rstd[b] = (float)(1.0 / sqrt(var + 1e-8));
    }
}

// --------- K6: adp = ((x1-mu)*rstd) @ Wxabs = rstd*(x1@W - mu*colsum(W)) ----------
__global__ __launch_bounds__(128) void k_adp(const float* __restrict__ Wx) {
    extern __shared__ float sm6[];
    float* Ws = sm6;                 // 128*128
    float* x1s = sm6 + Hh * Hh;      // 32*128
    int tid = threadIdx.x;
    int r0 = blockIdx.x * 32;
    for (int i = tid; i < Hh * Hh; i += 128) Ws[i] = Wx[i];
    for (int i = tid; i < 32 * Hh; i += 128) x1s[i] = g_x1[(size_t)r0 * Hh + i];
    __syncthreads();
    float cs = 0.f;
    for (int d = 0; d < Hh; ++d) cs += Ws[d * Hh + tid];
    for (int r = 0; r < 32; ++r) {
        int bn = r0 + r;
        int b = bn / Nn;
        float acc = 0.f;
        #pragma unroll 4
        for (int d = 0; d < Hh; ++d)
            acc = fmaf(x1s[r * Hh + d], Ws[d * Hh + tid], acc);
        g_adp[(size_t)bn * Hh + tid] = (acc - g_mu[b] * cs) * g_rstd[b];
    }
}

// ------ K7: adj = adp @ x1^T, fused relu + exact top-20 mask + row softmax --------
#define TM 16
#define CPT 4
#define NTH 512
__global__ __launch_bounds__(NTH) void k_adj(float* __restrict__ out) {
    extern __shared__ float sm7[];
    float* As = sm7;               // TM x 128
    float* outs = sm7 + TM * Hh;   // TM x 2048 (row-block results)
    int tid = threadIdx.x;
    int b = blockIdx.x / 125;
    int r0 = (blockIdx.x % 125) * TM;

    for (int i = tid; i < TM * Hh; i += NTH)
        As[i] = g_adp[((size_t)b * Nn + r0) * Hh + i];
    __syncthreads();

    int c0 = tid * CPT;
    float acc[TM][CPT];
    #pragma unroll
    for (int r = 0; r < TM; ++r)
        #pragma unroll
        for (int c = 0; c < CPT; ++c) acc[r][c] = 0.f;

    const float4* x1p = (const float4*)(g_x1 + (size_t)b * Nn * Hh);
    bool inb[CPT];
    #pragma unroll
    for (int c = 0; c < CPT; ++c) inb[c] = (c0 + c) < Nn;

    for (int kt = 0; kt < Hh / 4; ++kt) {
        float4 bv[CPT];
        #pragma unroll
        for (int c = 0; c < CPT; ++c)
            bv[c] = inb[c] ? x1p[(c0 + c) * (Hh / 4) + kt]
                           : make_float4(0.f, 0.f, 0.f, 0.f);
        #pragma unroll
        for (int r = 0; r < TM; ++r) {
            float4 a = *(const float4*)(As + r * Hh + kt * 4);  // broadcast LDS.128
            #pragma unroll
            for (int c = 0; c < CPT; ++c) {
                acc[r][c] = fmaf(a.x, bv[c].x, acc[r][c]);
                acc[r][c] = fmaf(a.y, bv[c].y, acc[r][c]);
                acc[r][c] = fmaf(a.z, bv[c].z, acc[r][c]);
                acc[r][c] = fmaf(a.w, bv[c].w, acc[r][c]);
            }
        }
    }
    #pragma unroll
    for (int r = 0; r < TM; ++r)
        #pragma unroll
        for (int c = 0; c < CPT; ++c)
            outs[r * 2048 + c0 + c] = fmaxf(acc[r][c], 0.f);  // relu here
    __syncthreads();

    // ---------------- epilogue: warp w owns row w ----------------
    int w = tid >> 5, l = tid & 31;
    const float* srow = outs + w * 2048;

    // phase 1: per-lane top-20 (registers only; branchless ternary insert)
    float ls[Kk];
    #pragma unroll
    for (int i = 0; i < Kk; ++i) ls[i] = -1.f;
    for (int j = 0; j < 63; ++j) {
        int c = l + 32 * j;
        if (c >= Nn) break;
        float v = srow[c];
        if (v > ls[Kk - 1]) {
            #pragma unroll
            for (int i = Kk - 1; i >= 1; --i)
                ls[i] = (v > ls[i - 1]) ? ls[i - 1] : ((v > ls[i]) ? v : ls[i]);
            ls[0] = fmaxf(ls[0], v);
        }
    }
    // phase 2: 20-round warp merge -> M (row max) and th (20th largest, w/ dups)
    float M = 0.f, th = 0.f;
    for (int it = 0; it < Kk; ++it) {
        float h = ls[0];
        float m = h;
        #pragma unroll
        for (int o = 16; o; o >>= 1)
            m = fmaxf(m, __shfl_xor_sync(0xffffffffu, m, o));
        if (it == 0) M = m;
        th = m;
        unsigned ball = __ballot_sync(0xffffffffu, h == m);
        if (l == (__ffs(ball) - 1)) {  // exactly one lane pops
            #pragma unroll
            for (int i = 0; i < Kk - 1; ++i) ls[i] = ls[i + 1];
            ls[Kk - 1] = -1.f;
        }
    }
    // phase 3: keep mask — all strictly-greater, then ties at th in index order
    unsigned long long keep = 0ull;
    int g = 0;
    for (int j = 0; j < 63; ++j) {
        int c = l + 32 * j;
        float v = (c < Nn) ? srow[c] : -1.f;
        if (v > th) { keep |= (1ull << j); ++g; }
    }
    #pragma unroll
    for (int o = 16; o; o >>= 1) g += __shfl_xor_sync(0xffffffffu, g, o);
    int need = Kk - g;  // >=1 always
    int taken = 0;
    for (int j = 0; j < 63; ++j) {
        int c = l + 32 * j;
        float v = (c < Nn) ? srow[c] : -1.f;
        bool eq = (v == th);
        unsigned ball = __ballot_sync(0xffffffffu, eq);
        int before = taken + __popc(ball & ((1u << l) - 1u));
        if (eq && before < need) keep |= (1ull << j);
        taken += __popc(ball);
        if (taken >= need) break;  // uniform exit
    }
    // phase 4: softmax denominator over all 2000 (masked-out entries are exact 0)
    float S = 0.f;
    for (int j = 0; j < 63; ++j) {
        int c = l + 32 * j;
        if (c >= Nn) break;
        float v = srow[c];
        float z = ((keep >> j) & 1ull) ? v : 0.f;
        S += expf(z - M);
    }
    #pragma unroll
    for (int o = 16; o; o >>= 1) S += __shfl_xor_sync(0xffffffffu, S, o);
    // phase 5: write
    float* orow = out + ((size_t)b * Nn + (r0 + w)) * (size_t)Nn;
    for (int j = 0; j < 63; ++j) {
        int c = l + 32 * j;
        if (c >= Nn) break;
        float v = srow[c];
        float z = ((keep >> j) & 1ull) ? v : 0.f;
        orow[c] = expf(z - M) / S;
    }
}

// ---------------------------------- launch ----------------------------------------
extern "C" void kernel_launch(void* const* d_in, const int* in_sizes, int n_in,
                              void* d_out, int out_size) {
    const float* x = (const float*)d_in[0];
    const float* Ex = (const float*)d_in[1];
    const float* nodes = (const float*)d_in[2];
    const float* Wd = (const float*)d_in[3];
    const float* Wx = (const float*)d_in[4];
    float* out = (float*)d_out;

    const int smem_adp = (Hh * Hh + 32 * Hh) * 4;          // 80 KB
    const int smem_adj = (TM * Hh + TM * 2048) * 4;        // 136 KB
    cudaFuncSetAttribute(k_adp, cudaFuncAttributeMaxDynamicSharedMemorySize, smem_adp);
    cudaFuncSetAttribute(k_adj, cudaFuncAttributeMaxDynamicSharedMemorySize, smem_adj);

    k_fft<<<Bb * Nn, 160>>>(x);
    k_colnorm<<<Bb * FLf, 256>>>();
    k_embed<<<Bb * Nn, 256>>>(Ex, nodes);
    k_x1<<<Nn, 128>>>(Wd);
    k_lnstats<<<Bb, 256>>>();
    k_adp<<<(Bb * Nn) / 32, 128, smem_adp>>>(Wx);
    k_adj<<<Bb * 125, NTH, smem_adj>>>(out);
}

// round 11
// speedup vs baseline: 2.0361x; 2.0361x over previous
#include <cuda_runtime.h>
#include <math.h>
#include <stdint.h>

// Problem constants
#define Bb 8
#define Tt 288
#define Nn 2000
#define FLf 145      // T/2+1
#define Ee 128
#define IDd 16
#define Dd 144       // E+ID
#define Hh 128
#define Kk 20
#define FPAD 160     // padded freq dim for DFT tiles (5 tiles of 32)

// ---------------- scratch (device globals; no allocation allowed) ----------------
__device__ __align__(16) float g_xf[Bb * Nn * FLf];   // |rfft|  [B,N,FL]
__device__ __align__(16) float g_A[Bb * FLf];         // node-dim norms
__device__ __align__(16) float g_xk[Bb * Nn * Dd];    // concat(xe, nodes)
__device__ __align__(16) float g_x1[Bb * Nn * Hh];    // relu(bmm)
__device__ __align__(16) float g_adp[Bb * Nn * Hh];   // LN-affine @ Wxabs
__device__ __align__(16) float2 g_W[Tt * FPAD];       // DFT twiddles (re,im)
__device__ float g_mu[Bb];
__device__ float g_rstd[Bb];

// ---------------- K0: twiddle table W[t][f] = exp(-2πi·(t·f mod T)/T) -------------
__global__ __launch_bounds__(256) void k_twiddle() {
    int i = blockIdx.x * 256 + threadIdx.x;
    if (i >= Tt * FPAD) return;
    int t = i / FPAD, f = i % FPAD;
    float2 w;
    if (f < FLf) {
        int ph = (t * f) % Tt;  // exact integer phase reduction
        float ang = -6.2831853071795864769f * (float)ph / (float)Tt;
        float s, c;
        sincosf(ang, &s, &c);
        w.x = c; w.y = s;
    } else {
        w.x = 0.f; w.y = 0.f;
    }
    g_W[i] = w;
}

// ---------------- K1: DFT magnitude as tiled GEMM  xf[b,n,f] = |Σ_t x·W| ----------
// tile: 128 n × 32 f, k-chunk 16; thread = 4n × 4f
#define DFT_TK 16
__global__ __launch_bounds__(256) void k_dft(const float* __restrict__ x) {
    __shared__ float Xs[DFT_TK][128];
    __shared__ float2 Ws[DFT_TK][32];
    int blk = blockIdx.x;
    int ft = blk % 5;
    int nt = (blk / 5) % 16;
    int b = blk / 80;
    int nbase = nt * 128, fbase = ft * 32;
    int tid = threadIdx.x;
    int tx = tid & 31, ty = tid >> 5;  // tx: n-group, ty: f-group
    int n0 = tx * 4, f0 = ty * 4;

    float accr[4][4], acci[4][4];
    #pragma unroll
    for (int i = 0; i < 4; ++i)
        #pragma unroll
        for (int j = 0; j < 4; ++j) { accr[i][j] = 0.f; acci[i][j] = 0.f; }

    for (int t0 = 0; t0 < Tt; t0 += DFT_TK) {
        __syncthreads();
        // stage X: 16 t-rows × 128 n (512 float4, 2/thread), n contiguous in gmem
        #pragma unroll
        for (int r = 0; r < 2; ++r) {
            int li = r * 256 + tid;
            int tt = li >> 5;
            int n4 = (li & 31) * 4;
            const float* src = x + (size_t)(b * Tt + t0 + tt) * Nn + nbase + n4;
            float4 v;
            if (nbase + n4 + 3 < Nn) {
                v = *(const float4*)src;
            } else {
                v.x = (nbase + n4 + 0 < Nn) ? src[0] : 0.f;
                v.y = (nbase + n4 + 1 < Nn) ? src[1] : 0.f;
                v.z = (nbase + n4 + 2 < Nn) ? src[2] : 0.f;
                v.w = (nbase + n4 + 3 < Nn) ? src[3] : 0.f;
            }
            *(float4*)&Xs[tt][n4] = v;
        }
        // stage W: 16 × 32 float2 (2/thread)
        #pragma unroll
        for (int r = 0; r < 2; ++r) {
            int li = r * 256 + tid;
            int tt = li >> 5;
            int ff = li & 31;
            Ws[tt][ff] = g_W[(t0 + tt) * FPAD + fbase + ff];
        }
        __syncthreads();
        #pragma unroll
        for (int tt = 0; tt < DFT_TK; ++tt) {
            float4 xv = *(const float4*)&Xs[tt][n0];   // conflict-free LDS.128
            float2 w0 = Ws[tt][f0 + 0];                // warp-broadcast
            float2 w1 = Ws[tt][f0 + 1];
            float2 w2 = Ws[tt][f0 + 2];
            float2 w3 = Ws[tt][f0 + 3];
            float xn[4] = {xv.x, xv.y, xv.z, xv.w};
            float2 wv[4] = {w0, w1, w2, w3};
            #pragma unroll
            for (int fi = 0; fi < 4; ++fi)
                #pragma unroll
                for (int ni = 0; ni < 4; ++ni) {
                    accr[fi][ni] = fmaf(xn[ni], wv[fi].x, accr[fi][ni]);
                    acci[fi][ni] = fmaf(xn[ni], wv[fi].y, acci[fi][ni]);
                }
        }
    }
    #pragma unroll
    for (int fi = 0; fi < 4; ++fi) {
        int f = fbase + f0 + fi;
        if (f >= FLf) continue;
        #pragma unroll
        for (int ni = 0; ni < 4; ++ni) {
            int n = nbase + n0 + ni;
            if (n < Nn) {
                float re = accr[fi][ni], im = acci[fi][ni];
                g_xf[((size_t)b * Nn + n) * FLf + f] = sqrtf(re * re + im * im);
            }
        }
    }
}

// ---------------- K2: norms over node dim: A[b,f] = max(||xf[b,:,f]||, eps) -------
__global__ __launch_bounds__(256) void k_colnorm() {
    int b = blockIdx.x / FLf, f = blockIdx.x % FLf;
    int tid = threadIdx.x;
    double s = 0.0;
    for (int n = tid; n < Nn; n += 256) {
        float v = g_xf[(b * Nn + n) * FLf + f];
        s += (double)v * (double)v;
    }
    __shared__ double red[256];
    red[tid] = s;
    __syncthreads();
    for (int o = 128; o; o >>= 1) {
        if (tid < o) red[tid] += red[tid + o];
        __syncthreads();
    }
    if (tid == 0) g_A[b * FLf + f] = fmaxf((float)sqrt(red[0]), 1e-12f);
}

// ---- K3: 8 nodes/block; Ex staged in smem once; normalize + embed + concat -------
__global__ __launch_bounds__(256) void k_embed8(const float* __restrict__ Ex,
                                                const float* __restrict__ nodes) {
    extern __shared__ float sm3[];
    float* Exs = sm3;                       // 145*128
    float* Ainv = sm3 + FLf * Ee;           // 145
    float* vs = Ainv + FLf;                 // 8*145
    float* rinv = vs + 8 * FLf;             // 8
    int blk = blockIdx.x;
    int b = blk / 250;
    int n0 = (blk % 250) * 8;
    int tid = threadIdx.x;
    int w = tid >> 5, l = tid & 31;

    for (int i = tid; i < FLf * Ee; i += 256) Exs[i] = Ex[i];
    if (tid < FLf) Ainv[tid] = 1.0f / g_A[b * FLf + tid];
    __syncthreads();

    // warp w owns node n0+w: compute v = xf/A, row norm (fp64), stash v
    {
        int n = n0 + w;
        const float* xr = g_xf + ((size_t)b * Nn + n) * FLf;
        double s = 0.0;
        for (int f = l; f < FLf; f += 32) {
            float val = xr[f] * Ainv[f];
            vs[w * FLf + f] = val;
            s += (double)val * (double)val;
        }
        #pragma unroll
        for (int o = 16; o; o >>= 1) s += __shfl_xor_sync(0xffffffffu, s, o);
        if (l == 0) rinv[w] = 1.0f / fmaxf((float)sqrt(s), 1e-12f);
    }
    __syncthreads();

    // thread (g, e): g = tid>>7 handles nodes g, g+2, g+4, g+6 for column e
    int e = tid & 127, g = tid >> 7;
    float acc[4] = {0.f, 0.f, 0.f, 0.f};
    for (int f = 0; f < FLf; ++f) {
        float ex = Exs[f * Ee + e];         // conflict-free
        #pragma unroll
        for (int q = 0; q < 4; ++q)
            acc[q] = fmaf(vs[(g + 2 * q) * FLf + f], ex, acc[q]);  // broadcast
    }
    #pragma unroll
    for (int q = 0; q < 4; ++q) {
        int node = g + 2 * q;
        g_xk[((size_t)b * Nn + n0 + node) * Dd + e] = acc[q] * rinv[node];
    }
    // identity part
    if (tid < 128) {
        int node = tid >> 4, id = tid & 15;
        g_xk[((size_t)b * Nn + n0 + node) * Dd + Ee + id] =
            nodes[(n0 + node) * IDd + id];
    }
}

// ---------------- K4: x1 = relu(xk @ Wd[n]); 2 nodes per block -------------------
__global__ __launch_bounds__(256) void k_x1(const float* __restrict__ Wd) {
    __shared__ float xs[2][Bb][Dd];
    int tid = threadIdx.x;
    int half = tid >> 7, t2 = tid & 127;
    int n = blockIdx.x * 2 + half;
    for (int i = tid; i < 2 * Bb * Dd; i += 256) {
        int nn = i / (Bb * Dd);
        int rem = i % (Bb * Dd);
        int b = rem / Dd, d = rem % Dd;
        xs[nn][b][d] = g_xk[((size_t)b * Nn + blockIdx.x * 2 + nn) * Dd + d];
    }
    __syncthreads();
    float acc[Bb];
    #pragma unroll
    for (int b = 0; b < Bb; ++b) acc[b] = 0.f;
    const float* W = Wd + (size_t)n * Dd * Hh + t2;
    #pragma unroll 8
    for (int d = 0; d < Dd; ++d) {
        float wv = W[d * Hh];
        #pragma unroll
        for (int b = 0; b < Bb; ++b) acc[b] = fmaf(xs[half][b][d], wv, acc[b]);
    }
    #pragma unroll
    for (int b = 0; b < Bb; ++b)
        g_x1[((size_t)b * Nn + n) * Hh + t2] = fmaxf(acc[b], 0.f);
}

// ---------------- K5: LayerNorm stats per batch (fp64 accumulation) ---------------
__global__ __launch_bounds__(256) void k_lnstats() {
    int b = blockIdx.x, tid = threadIdx.x;
    double s = 0.0, s2 = 0.0;
    const float* p = g_x1 + (size_t)b * Nn * Hh;
    for (int i = tid; i < Nn * Hh; i += 256) {
        double v = (double)p[i];
        s += v;
        s2 += v * v;
    }
    __shared__ double r1[256];
    __shared__ double r2[256];
    r1[tid] = s;
    r2[tid] = s2;
    __syncthreads();
    for (int o = 128; o; o >>= 1) {
        if (tid < o) { r1[tid] += r1[tid + o]; r2[tid] += r2[tid + o]; }
        __syncthreads();
    }
    if (tid == 0) {
        double cnt = (double)(Nn * Hh);
        double mu = r1[0] / cnt;
        double var = r2[0] / cnt - mu * mu;
        g_mu[b] = (float)mu;
        g_rstd[b] = (float)(1.0 / sqrt(var + 1e-8));
    }
}

// --------- K6: adp = ((x1-mu)*rstd) @ Wxabs = rstd*(x1@W - mu*colsum(W)) ----------
__global__ __launch_bounds__(128) void k_adp(const float* __restrict__ Wx) {
    extern __shared__ float sm6[];
    float* Ws = sm6;                 // 128*128
    float* x1s = sm6 + Hh * Hh;      // 32*128
    int tid = threadIdx.x;
    int r0 = blockIdx.x * 32;
    for (int i = tid; i < Hh * Hh; i += 128) Ws[i] = Wx[i];
    for (int i = tid; i < 32 * Hh; i += 128) x1s[i] = g_x1[(size_t)r0 * Hh + i];
    __syncthreads();
    float cs = 0.f;
    for (int d = 0; d < Hh; ++d) cs += Ws[d * Hh + tid];
    for (int r = 0; r < 32; ++r) {
        int bn = r0 + r;
        int b = bn / Nn;
        float acc = 0.f;
        #pragma unroll 4
        for (int d = 0; d < Hh; ++d)
            acc = fmaf(x1s[r * Hh + d], Ws[d * Hh + tid], acc);
        g_adp[(size_t)bn * Hh + tid] = (acc - g_mu[b] * cs) * g_rstd[b];
    }
}

// ------ K7: adj = adp @ x1^T, fused relu + exact top-20 mask + row softmax --------
#define TM 16
#define CPT 4
#define NTH 512
__global__ __launch_bounds__(NTH) void k_adj(float* __restrict__ out) {
    extern __shared__ float sm7[];
    float* As = sm7;               // TM x 128
    float* outs = sm7 + TM * Hh;   // TM x 2048
    int tid = threadIdx.x;
    int b = blockIdx.x / 125;
    int r0 = (blockIdx.x % 125) * TM;

    for (int i = tid; i < TM * Hh; i += NTH)
        As[i] = g_adp[((size_t)b * Nn + r0) * Hh + i];
    __syncthreads();

    int c0 = tid * CPT;
    float acc[TM][CPT];
    #pragma unroll
    for (int r = 0; r < TM; ++r)
        #pragma unroll
        for (int c = 0; c < CPT; ++c) acc[r][c] = 0.f;

    const float4* x1p = (const float4*)(g_x1 + (size_t)b * Nn * Hh);
    bool inb[CPT];
    #pragma unroll
    for (int c = 0; c < CPT; ++c) inb[c] = (c0 + c) < Nn;

    for (int kt = 0; kt < Hh / 4; ++kt) {
        float4 bv[CPT];
        #pragma unroll
        for (int c = 0; c < CPT; ++c)
            bv[c] = inb[c] ? x1p[(c0 + c) * (Hh / 4) + kt]
                           : make_float4(0.f, 0.f, 0.f, 0.f);
        #pragma unroll
        for (int r = 0; r < TM; ++r) {
            float4 a = *(const float4*)(As + r * Hh + kt * 4);
            #pragma unroll
            for (int c = 0; c < CPT; ++c) {
                acc[r][c] = fmaf(a.x, bv[c].x, acc[r][c]);
                acc[r][c] = fmaf(a.y, bv[c].y, acc[r][c]);
                acc[r][c] = fmaf(a.z, bv[c].z, acc[r][c]);
                acc[r][c] = fmaf(a.w, bv[c].w, acc[r][c]);
            }
        }
    }
    #pragma unroll
    for (int r = 0; r < TM; ++r)
        #pragma unroll
        for (int c = 0; c < CPT; ++c)
            outs[r * 2048 + c0 + c] = fmaxf(acc[r][c], 0.f);
    __syncthreads();

    // ---------------- epilogue: warp w owns row w ----------------
    int w = tid >> 5, l = tid & 31;
    const float* srow = outs + w * 2048;

    float ls[Kk];
    #pragma unroll
    for (int i = 0; i < Kk; ++i) ls[i] = -1.f;
    for (int j = 0; j < 63; ++j) {
        int c = l + 32 * j;
        if (c >= Nn) break;
        float v = srow[c];
        if (v > ls[Kk - 1]) {
            #pragma unroll
            for (int i = Kk - 1; i >= 1; --i)
                ls[i] = (v > ls[i - 1]) ? ls[i - 1] : ((v > ls[i]) ? v : ls[i]);
            ls[0] = fmaxf(ls[0], v);
        }
    }
    float M = 0.f, th = 0.f;
    for (int it = 0; it < Kk; ++it) {
        float h = ls[0];
        float m = h;
        #pragma unroll
        for (int o = 16; o; o >>= 1)
            m = fmaxf(m, __shfl_xor_sync(0xffffffffu, m, o));
        if (it == 0) M = m;
        th = m;
        unsigned ball = __ballot_sync(0xffffffffu, h == m);
        if (l == (__ffs(ball) - 1)) {
            #pragma unroll
            for (int i = 0; i < Kk - 1; ++i) ls[i] = ls[i + 1];
            ls[Kk - 1] = -1.f;
        }
    }
    unsigned long long keep = 0ull;
    int g = 0;
    for (int j = 0; j < 63; ++j) {
        int c = l + 32 * j;
        float v = (c < Nn) ? srow[c] : -1.f;
        if (v > th) { keep |= (1ull << j); ++g; }
    }
    #pragma unroll
    for (int o = 16; o; o >>= 1) g += __shfl_xor_sync(0xffffffffu, g, o);
    int need = Kk - g;
    int taken = 0;
    for (int j = 0; j < 63; ++j) {
        int c = l + 32 * j;
        float v = (c < Nn) ? srow[c] : -1.f;
        bool eq = (v == th);
        unsigned ball = __ballot_sync(0xffffffffu, eq);
        int before = taken + __popc(ball & ((1u << l) - 1u));
        if (eq && before < need) keep |= (1ull << j);
        taken += __popc(ball);
        if (taken >= need) break;
    }
    float S = 0.f;
    for (int j = 0; j < 63; ++j) {
        int c = l + 32 * j;
        if (c >= Nn) break;
        float v = srow[c];
        float z = ((keep >> j) & 1ull) ? v : 0.f;
        S += expf(z - M);
    }
    #pragma unroll
    for (int o = 16; o; o >>= 1) S += __shfl_xor_sync(0xffffffffu, S, o);
    float* orow = out + ((size_t)b * Nn + (r0 + w)) * (size_t)Nn;
    for (int j = 0; j < 63; ++j) {
        int c = l + 32 * j;
        if (c >= Nn) break;
        float v = srow[c];
        float z = ((keep >> j) & 1ull) ? v : 0.f;
        orow[c] = expf(z - M) / S;
    }
}

// ---------------------------------- launch ----------------------------------------
extern "C" void kernel_launch(void* const* d_in, const int* in_sizes, int n_in,
                              void* d_out, int out_size) {
    const float* x = (const float*)d_in[0];
    const float* Ex = (const float*)d_in[1];
    const float* nodes = (const float*)d_in[2];
    const float* Wd = (const float*)d_in[3];
    const float* Wx = (const float*)d_in[4];
    float* out = (float*)d_out;

    const int smem_emb = (FLf * Ee + FLf + 8 * FLf + 8) * 4;   // ~79.6 KB
    const int smem_adp = (Hh * Hh + 32 * Hh) * 4;              // 80 KB
    const int smem_adj = (TM * Hh + TM * 2048) * 4;            // 136 KB
    cudaFuncSetAttribute(k_embed8, cudaFuncAttributeMaxDynamicSharedMemorySize, smem_emb);
    cudaFuncSetAttribute(k_adp, cudaFuncAttributeMaxDynamicSharedMemorySize, smem_adp);
    cudaFuncSetAttribute(k_adj, cudaFuncAttributeMaxDynamicSharedMemorySize, smem_adj);

    k_twiddle<<<(Tt * FPAD + 255) / 256, 256>>>();
    k_dft<<<Bb * 16 * 5, 256>>>(x);
    k_colnorm<<<Bb * FLf, 256>>>();
    k_embed8<<<Bb * 250, 256, smem_emb>>>(Ex, nodes);
    k_x1<<<Nn / 2, 256>>>(Wd);
    k_lnstats<<<Bb, 256>>>();
    k_adp<<<(Bb * Nn) / 32, 128, smem_adp>>>(Wx);
    k_adj<<<Bb * 125, NTH, smem_adj>>>(out);
}

// round 16
// speedup vs baseline: 2.5110x; 1.2332x over previous
#include <cuda_runtime.h>
#include <math.h>
#include <stdint.h>

// Problem constants
#define Bb 8
#define Tt 288
#define Nn 2000
#define FLf 145      // T/2+1
#define Ee 128
#define IDd 16
#define Dd 144       // E+ID
#define Hh 128
#define Kk 20
#define FPAD 160     // padded freq dim (10 chunks of 16)

typedef unsigned long long ull;

// ---- packed fp32x2 helpers (FFMA2 path; SASS: one FMA-pipe instr for 2 FMAs) ----
__device__ __forceinline__ void ffma2(ull& d, ull a, ull b) {
    asm("fma.rn.f32x2 %0, %1, %2, %0;" : "+l"(d) : "l"(a), "l"(b));
}
__device__ __forceinline__ ull pack2(float lo, float hi) {
    ull r;
    asm("mov.b64 %0, {%1, %2};" : "=l"(r) : "f"(lo), "f"(hi));
    return r;
}
__device__ __forceinline__ float2 unpack2(ull v) {
    float2 f;
    asm("mov.b64 {%0, %1}, %2;" : "=f"(f.x), "=f"(f.y) : "l"(v));
    return f;
}

// ---------------- scratch (device globals; no allocation allowed) ----------------
__device__ __align__(16) float g_xfT[Bb * FLf * Nn];  // |rfft| TRANSPOSED [B,FL,N]
__device__ __align__(16) float g_A[Bb * FLf];         // node-dim norms
__device__ __align__(16) float g_rinv[Bb * Nn];       // 1/row-norm
__device__ __align__(16) float g_xk[Bb * Nn * Dd];    // concat(xe, nodes)
__device__ __align__(16) float g_x1[Bb * Nn * Hh];    // relu(bmm)
__device__ __align__(16) float g_adp[Bb * Nn * Hh];   // LN-affine @ Wxabs
__device__ __align__(16) float2 g_W[Tt * FPAD];       // DFT twiddles (re,im)
__device__ double g_part[Bb * 32 * 2];                // LN partials
__device__ float g_mu[Bb];
__device__ float g_rstd[Bb];

// ---------------- K0: twiddle table W[t][f] = exp(-2πi·(t·f mod T)/T) -------------
__global__ __launch_bounds__(256) void k_twiddle() {
    int i = blockIdx.x * 256 + threadIdx.x;
    if (i >= Tt * FPAD) return;
    int t = i / FPAD, f = i % FPAD;
    float2 w;
    if (f < FLf) {
        int ph = (t * f) % Tt;  // exact integer phase reduction
        float ang = -6.2831853071795864769f * (float)ph / (float)Tt;
        float s, c;
        sincosf(ang, &s, &c);
        w.x = c; w.y = s;
    } else {
        w.x = 0.f; w.y = 0.f;
    }
    g_W[i] = w;
}

// ---------------- K1: DFT magnitude as tiled GEMM (FFMA2 re/im pairs) -------------
// tile: 128 n × 32 f, k-chunk 16; thread = 4n × 4f; output TRANSPOSED [f][n]
#define DFT_TK 16
__global__ __launch_bounds__(256) void k_dft(const float* __restrict__ x) {
    __shared__ float Xs[DFT_TK][128];
    __shared__ float2 Ws[DFT_TK][32];
    int blk = blockIdx.x;
    int ft = blk % 5;
    int nt = (blk / 5) % 16;
    int b = blk / 80;
    int nbase = nt * 128, fbase = ft * 32;
    int tid = threadIdx.x;
    int tx = tid & 31, ty = tid >> 5;
    int n0 = tx * 4, f0 = ty * 4;

    ull acc[4][4];  // [fi][ni] packed (re,im)
    #pragma unroll
    for (int i = 0; i < 4; ++i)
        #pragma unroll
        for (int j = 0; j < 4; ++j) acc[i][j] = pack2(0.f, 0.f);

    for (int t0 = 0; t0 < Tt; t0 += DFT_TK) {
        __syncthreads();
        #pragma unroll
        for (int r = 0; r < 2; ++r) {
            int li = r * 256 + tid;
            int tt = li >> 5;
            int n4 = (li & 31) * 4;
            const float* src = x + (size_t)(b * Tt + t0 + tt) * Nn + nbase + n4;
            float4 v;
            if (nbase + n4 + 3 < Nn) {
                v = *(const float4*)src;
            } else {
                v.x = (nbase + n4 + 0 < Nn) ? src[0] : 0.f;
                v.y = (nbase + n4 + 1 < Nn) ? src[1] : 0.f;
                v.z = (nbase + n4 + 2 < Nn) ? src[2] : 0.f;
                v.w = (nbase + n4 + 3 < Nn) ? src[3] : 0.f;
            }
            *(float4*)&Xs[tt][n4] = v;
        }
        #pragma unroll
        for (int r = 0; r < 2; ++r) {
            int li = r * 256 + tid;
            Ws[li >> 5][li & 31] = g_W[(t0 + (li >> 5)) * FPAD + fbase + (li & 31)];
        }
        __syncthreads();
        #pragma unroll
        for (int tt = 0; tt < DFT_TK; ++tt) {
            float4 xv = *(const float4*)&Xs[tt][n0];        // conflict-free LDS.128
            ull x2[4] = {pack2(xv.x, xv.x), pack2(xv.y, xv.y),
                         pack2(xv.z, xv.z), pack2(xv.w, xv.w)};
            #pragma unroll
            for (int fi = 0; fi < 4; ++fi) {
                ull wp = *(const ull*)&Ws[tt][f0 + fi];      // broadcast LDS.64
                #pragma unroll
                for (int ni = 0; ni < 4; ++ni) ffma2(acc[fi][ni], x2[ni], wp);
            }
        }
    }
    #pragma unroll
    for (int fi = 0; fi < 4; ++fi) {
        int f = fbase + f0 + fi;
        if (f >= FLf) continue;
        if (nbase + n0 + 3 < Nn) {
            float4 o;
            float2 v0 = unpack2(acc[fi][0]);
            float2 v1 = unpack2(acc[fi][1]);
            float2 v2 = unpack2(acc[fi][2]);
            float2 v3 = unpack2(acc[fi][3]);
            o.x = sqrtf(v0.x * v0.x + v0.y * v0.y);
            o.y = sqrtf(v1.x * v1.x + v1.y * v1.y);
            o.z = sqrtf(v2.x * v2.x + v2.y * v2.y);
            o.w = sqrtf(v3.x * v3.x + v3.y * v3.y);
            *(float4*)&g_xfT[((size_t)b * FLf + f) * Nn + nbase + n0] = o;
        }
    }
}

// ------- K2: node-dim norms (coalesced on transposed layout) ----------------------
__global__ __launch_bounds__(256) void k_colnorm() {
    int b = blockIdx.x / FLf, f = blockIdx.x % FLf;
    int tid = threadIdx.x;
    const float* p = g_xfT + ((size_t)b * FLf + f) * Nn;
    double s = 0.0;
    for (int n = tid; n < Nn; n += 256) {
        float v = p[n];
        s += (double)v * (double)v;
    }
    __shared__ double red[256];
    red[tid] = s;
    __syncthreads();
    for (int o = 128; o; o >>= 1) {
        if (tid < o) red[tid] += red[tid + o];
        __syncthreads();
    }
    if (tid == 0) g_A[b * FLf + f] = fmaxf((float)sqrt(red[0]), 1e-12f);
}

// ------- K2b: row norms on col-normalized values + identity fill ------------------
__global__ __launch_bounds__(256) void k_rownorm(const float* __restrict__ nodes) {
    __shared__ float Ainv[FLf];
    int b = blockIdx.x >> 3;
    int n = (blockIdx.x & 7) * 256 + threadIdx.x;
    if (threadIdx.x < FLf) Ainv[threadIdx.x] = 1.0f / g_A[b * FLf + threadIdx.x];
    __syncthreads();
    if (n >= Nn) return;
    double s = 0.0;
    for (int f = 0; f < FLf; ++f) {
        float v = g_xfT[((size_t)b * FLf + f) * Nn + n] * Ainv[f];  // coalesced
        s += (double)v * (double)v;
    }
    g_rinv[b * Nn + n] = 1.0f / fmaxf((float)sqrt(s), 1e-12f);
    // identity part of xk
    float* dst = g_xk + ((size_t)b * Nn + n) * Dd + Ee;
    const float4* src = (const float4*)(nodes + n * IDd);
    #pragma unroll
    for (int q = 0; q < 4; ++q) ((float4*)dst)[q] = src[q];
}

// ------- K3: embed GEMM  xe = rinv ⊙ (xfT^T @ (Ainv ⊙ Ex))  (FFMA2) ---------------
// tile: 128 n × 32 e, k-chunk 16 over FPAD=160 (zero-padded)
__global__ __launch_bounds__(256) void k_embed(const float* __restrict__ Ex) {
    __shared__ float Xs[DFT_TK][128];
    __shared__ float Es[DFT_TK][32];
    __shared__ float Ainv[FPAD];
    int blk = blockIdx.x;
    int et = blk & 3;
    int nt = (blk >> 2) & 15;
    int b = blk >> 6;
    int nbase = nt * 128, ebase = et * 32;
    int tid = threadIdx.x;
    int tx = tid & 31, ty = tid >> 5;
    int n0 = tx * 4, e0 = ty * 4;

    if (tid < FPAD) Ainv[tid] = (tid < FLf) ? (1.0f / g_A[b * FLf + tid]) : 0.f;
    __syncthreads();

    ull acc01[4], acc23[4];  // [ni], e-pairs (e0,e1) and (e2,e3)
    #pragma unroll
    for (int i = 0; i < 4; ++i) { acc01[i] = pack2(0.f, 0.f); acc23[i] = pack2(0.f, 0.f); }

    for (int t0 = 0; t0 < FPAD; t0 += DFT_TK) {
        __syncthreads();
        #pragma unroll
        for (int r = 0; r < 2; ++r) {
            int li = r * 256 + tid;
            int tt = li >> 5;
            int n4 = (li & 31) * 4;
            int f = t0 + tt;
            float4 v = make_float4(0.f, 0.f, 0.f, 0.f);
            if (f < FLf && nbase + n4 + 3 < Nn)
                v = *(const float4*)&g_xfT[((size_t)b * FLf + f) * Nn + nbase + n4];
            else if (f < FLf) {
                const float* src = &g_xfT[((size_t)b * FLf + f) * Nn + nbase + n4];
                if (nbase + n4 + 0 < Nn) v.x = src[0];
                if (nbase + n4 + 1 < Nn) v.y = src[1];
                if (nbase + n4 + 2 < Nn) v.z = src[2];
                if (nbase + n4 + 3 < Nn) v.w = src[3];
            }
            *(float4*)&Xs[tt][n4] = v;
        }
        #pragma unroll
        for (int r = 0; r < 2; ++r) {
            int li = r * 256 + tid;
            int tt = li >> 5, e = li & 31;
            int f = t0 + tt;
            Es[tt][e] = (f < FLf) ? Ainv[f] * Ex[f * Ee + ebase + e] : 0.f;
        }
        __syncthreads();
        #pragma unroll
        for (int tt = 0; tt < DFT_TK; ++tt) {
            float4 xv = *(const float4*)&Xs[tt][n0];
            ull e01 = *(const ull*)&Es[tt][e0];       // broadcast LDS.64
            ull e23 = *(const ull*)&Es[tt][e0 + 2];
            ull x2[4] = {pack2(xv.x, xv.x), pack2(xv.y, xv.y),
                         pack2(xv.z, xv.z), pack2(xv.w, xv.w)};
            #pragma unroll
            for (int ni = 0; ni < 4; ++ni) {
                ffma2(acc01[ni], x2[ni], e01);
                ffma2(acc23[ni], x2[ni], e23);
            }
        }
    }
    #pragma unroll
    for (int ni = 0; ni < 4; ++ni) {
        int n = nbase + n0 + ni;
        if (n >= Nn) continue;
        float rv = g_rinv[b * Nn + n];
        float2 u01 = unpack2(acc01[ni]);
        float2 u23 = unpack2(acc23[ni]);
        float4 o = make_float4(u01.x * rv, u01.y * rv, u23.x * rv, u23.y * rv);
        *(float4*)&g_xk[((size_t)b * Nn + n) * Dd + ebase + e0] = o;
    }
}

// ---------------- K4: x1 = relu(xk @ Wd[n]); 2 nodes per block --------------------
__global__ __launch_bounds__(256) void k_x1(const float* __restrict__ Wd) {
    __shared__ float xs[2][Bb][Dd];
    int tid = threadIdx.x;
    int half = tid >> 7, t2 = tid & 127;
    int n = blockIdx.x * 2 + half;
    for (int i = tid; i < 2 * Bb * Dd; i += 256) {
        int nn = i / (Bb * Dd);
        int rem = i % (Bb * Dd);
        int b = rem / Dd, d = rem % Dd;
        xs[nn][b][d] = g_xk[((size_t)b * Nn + blockIdx.x * 2 + nn) * Dd + d];
    }
    __syncthreads();
    float acc[Bb];
    #pragma unroll
    for (int b = 0; b < Bb; ++b) acc[b] = 0.f;
    const float* W = Wd + (size_t)n * Dd * Hh + t2;
    #pragma unroll 8
    for (int d = 0; d < Dd; ++d) {
        float wv = W[d * Hh];
        #pragma unroll
        for (int b = 0; b < Bb; ++b) acc[b] = fmaf(xs[half][b][d], wv, acc[b]);
    }
    #pragma unroll
    for (int b = 0; b < Bb; ++b)
        g_x1[((size_t)b * Nn + n) * Hh + t2] = fmaxf(acc[b], 0.f);
}

// ---------------- K5: LayerNorm stats, 2-stage deterministic ----------------------
__global__ __launch_bounds__(256) void k_ln1() {
    int b = blockIdx.x >> 5, i = blockIdx.x & 31;
    int tid = threadIdx.x;
    const float* p = g_x1 + (size_t)b * Nn * Hh + i * 8000;
    double s = 0.0, s2 = 0.0;
    for (int j = tid; j < 8000; j += 256) {
        double v = (double)p[j];
        s += v;
        s2 += v * v;
    }
    __shared__ double r1[256];
    __shared__ double r2[256];
    r1[tid] = s;
    r2[tid] = s2;
    __syncthreads();
    for (int o = 128; o; o >>= 1) {
        if (tid < o) { r1[tid] += r1[tid + o]; r2[tid] += r2[tid + o]; }
        __syncthreads();
    }
    if (tid == 0) {
        g_part[blockIdx.x * 2 + 0] = r1[0];
        g_part[blockIdx.x * 2 + 1] = r2[0];
    }
}
__global__ void k_ln2() {
    int b = blockIdx.x;
    if (threadIdx.x != 0) return;
    double s = 0.0, s2 = 0.0;
    for (int i = 0; i < 32; ++i) {       // fixed order -> deterministic
        s += g_part[(b * 32 + i) * 2 + 0];
        s2 += g_part[(b * 32 + i) * 2 + 1];
    }
    double cnt = (double)(Nn * Hh);
    double mu = s / cnt;
    double var = s2 / cnt - mu * mu;
    g_mu[b] = (float)mu;
    g_rstd[b] = (float)(1.0 / sqrt(var + 1e-8));
}

// --------- K6: adp = ((x1-mu)*rstd) @ Wxabs = rstd*(x1@W - mu*colsum(W)) ----------
__global__ __launch_bounds__(128) void k_adp(const float* __restrict__ Wx) {
    extern __shared__ float sm6[];
    float* Ws = sm6;                 // 128*128
    float* x1s = sm6 + Hh * Hh;      // 32*128
    int tid = threadIdx.x;
    int r0 = blockIdx.x * 32;
    for (int i = tid; i < Hh * Hh; i += 128) Ws[i] = Wx[i];
    for (int i = tid; i < 32 * Hh; i += 128) x1s[i] = g_x1[(size_t)r0 * Hh + i];
    __syncthreads();
    float cs = 0.f;
    for (int d = 0; d < Hh; ++d) cs += Ws[d * Hh + tid];
    for (int r = 0; r < 32; ++r) {
        int bn = r0 + r;
        int b = bn / Nn;
        float acc = 0.f;
        #pragma unroll 4
        for (int d = 0; d < Hh; ++d)
            acc = fmaf(x1s[r * Hh + d], Ws[d * Hh + tid], acc);
        g_adp[(size_t)bn * Hh + tid] = (acc - g_mu[b] * cs) * g_rstd[b];
    }
}

// ------ K7: adj = adp @ x1^T (FFMA2) + fused relu/top-20/softmax ------------------
#define TM 16
#define CPT 4
#define NTH 512
__global__ __launch_bounds__(NTH) void k_adj(float* __restrict__ out) {
    extern __shared__ float sm7[];
    float* As = sm7;               // TM x 128
    float* outs = sm7 + TM * Hh;   // TM x 2048
    int tid = threadIdx.x;
    int b = blockIdx.x / 125;
    int r0 = (blockIdx.x % 125) * TM;

    for (int i = tid; i < TM * Hh; i += NTH)
        As[i] = g_adp[((size_t)b * Nn + r0) * Hh + i];
    __syncthreads();

    int c0 = tid * CPT;
    ull acc01[TM], acc23[TM];      // per row: c-pairs (c0,c1), (c2,c3)
    #pragma unroll
    for (int r = 0; r < TM; ++r) { acc01[r] = pack2(0.f, 0.f); acc23[r] = pack2(0.f, 0.f); }

    const float4* x1p = (const float4*)(g_x1 + (size_t)b * Nn * Hh);
    bool inb[CPT];
    #pragma unroll
    for (int c = 0; c < CPT; ++c) inb[c] = (c0 + c) < Nn;

    for (int kt = 0; kt < Hh / 4; ++kt) {
        float4 bv[CPT];
        #pragma unroll
        for (int c = 0; c < CPT; ++c)
            bv[c] = inb[c] ? x1p[(c0 + c) * (Hh / 4) + kt]
                           : make_float4(0.f, 0.f, 0.f, 0.f);
        ull bk01[4], bk23[4];  // per k-elem, c-pairs
        bk01[0] = pack2(bv[0].x, bv[1].x); bk23[0] = pack2(bv[2].x, bv[3].x);
        bk01[1] = pack2(bv[0].y, bv[1].y); bk23[1] = pack2(bv[2].y, bv[3].y);
        bk01[2] = pack2(bv[0].z, bv[1].z); bk23[2] = pack2(bv[2].z, bv[3].z);
        bk01[3] = pack2(bv[0].w, bv[1].w); bk23[3] = pack2(bv[2].w, bv[3].w);
        #pragma unroll
        for (int r = 0; r < TM; ++r) {
            float4 a = *(const float4*)(As + r * Hh + kt * 4);  // broadcast LDS.128
            ull a0 = pack2(a.x, a.x);
            ffma2(acc01[r], a0, bk01[0]); ffma2(acc23[r], a0, bk23[0]);
            ull a1 = pack2(a.y, a.y);
            ffma2(acc01[r], a1, bk01[1]); ffma2(acc23[r], a1, bk23[1]);
            ull a2 = pack2(a.z, a.z);
            ffma2(acc01[r], a2, bk01[2]); ffma2(acc23[r], a2, bk23[2]);
            ull a3 = pack2(a.w, a.w);
            ffma2(acc01[r], a3, bk01[3]); ffma2(acc23[r], a3, bk23[3]);
        }
    }
    #pragma unroll
    for (int r = 0; r < TM; ++r) {
        float2 u01 = unpack2(acc01[r]);
        float2 u23 = unpack2(acc23[r]);
        outs[r * 2048 + c0 + 0] = fmaxf(u01.x, 0.f);
        outs[r * 2048 + c0 + 1] = fmaxf(u01.y, 0.f);
        outs[r * 2048 + c0 + 2] = fmaxf(u23.x, 0.f);
        outs[r * 2048 + c0 + 3] = fmaxf(u23.y, 0.f);
    }
    __syncthreads();

    // ---------------- epilogue: warp w owns row w ----------------
    int w = tid >> 5, l = tid & 31;
    const float* srow = outs + w * 2048;

    float ls[Kk];
    #pragma unroll
    for (int i = 0; i < Kk; ++i) ls[i] = -1.f;
    for (int j = 0; j < 63; ++j) {
        int c = l + 32 * j;
        if (c >= Nn) break;
        float v = srow[c];
        if (v > ls[Kk - 1]) {
            #pragma unroll
            for (int i = Kk - 1; i >= 1; --i)
                ls[i] = (v > ls[i - 1]) ? ls[i - 1] : ((v > ls[i]) ? v : ls[i]);
            ls[0] = fmaxf(ls[0], v);
        }
    }
    float M = 0.f, th = 0.f;
    for (int it = 0; it < Kk; ++it) {
        float h = ls[0];
        float m = h;
        #pragma unroll
        for (int o = 16; o; o >>= 1)
            m = fmaxf(m, __shfl_xor_sync(0xffffffffu, m, o));
        if (it == 0) M = m;
        th = m;
        unsigned ball = __ballot_sync(0xffffffffu, h == m);
        if (l == (__ffs(ball) - 1)) {
            #pragma unroll
            for (int i = 0; i < Kk - 1; ++i) ls[i] = ls[i + 1];
            ls[Kk - 1] = -1.f;
        }
    }
    unsigned long long keep = 0ull;
    int g = 0;
    for (int j = 0; j < 63; ++j) {
        int c = l + 32 * j;
        float v = (c < Nn) ? srow[c] : -1.f;
        if (v > th) { keep |= (1ull << j); ++g; }
    }
    #pragma unroll
    for (int o = 16; o; o >>= 1) g += __shfl_xor_sync(0xffffffffu, g, o);
    int need = Kk - g;
    int taken = 0;
    for (int j = 0; j < 63; ++j) {
        int c = l + 32 * j;
        float v = (c < Nn) ? srow[c] : -1.f;
        bool eq = (v == th);
        unsigned ball = __ballot_sync(0xffffffffu, eq);
        int before = taken + __popc(ball & ((1u << l) - 1u));
        if (eq && before < need) keep |= (1ull << j);
        taken += __popc(ball);
        if (taken >= need) break;
    }
    float S = 0.f;
    for (int j = 0; j < 63; ++j) {
        int c = l + 32 * j;
        if (c >= Nn) break;
        float v = srow[c];
        float z = ((keep >> j) & 1ull) ? v : 0.f;
        S += expf(z - M);
    }
    #pragma unroll
    for (int o = 16; o; o >>= 1) S += __shfl_xor_sync(0xffffffffu, S, o);
    float* orow = out + ((size_t)b * Nn + (r0 + w)) * (size_t)Nn;
    for (int j = 0; j < 63; ++j) {
        int c = l + 32 * j;
        if (c >= Nn) break;
        float v = srow[c];
        float z = ((keep >> j) & 1ull) ? v : 0.f;
        orow[c] = expf(z - M) / S;
    }
}

// ---------------------------------- launch ----------------------------------------
extern "C" void kernel_launch(void* const* d_in, const int* in_sizes, int n_in,
                              void* d_out, int out_size) {
    const float* x = (const float*)d_in[0];
    const float* Ex = (const float*)d_in[1];
    const float* nodes = (const float*)d_in[2];
    const float* Wd = (const float*)d_in[3];
    const float* Wx = (const float*)d_in[4];
    float* out = (float*)d_out;

    const int smem_adp = (Hh * Hh + 32 * Hh) * 4;              // 80 KB
    const int smem_adj = (TM * Hh + TM * 2048) * 4;            // 136 KB
    cudaFuncSetAttribute(k_adp, cudaFuncAttributeMaxDynamicSharedMemorySize, smem_adp);
    cudaFuncSetAttribute(k_adj, cudaFuncAttributeMaxDynamicSharedMemorySize, smem_adj);

    k_twiddle<<<(Tt * FPAD + 255) / 256, 256>>>();
    k_dft<<<Bb * 16 * 5, 256>>>(x);
    k_colnorm<<<Bb * FLf, 256>>>();
    k_rownorm<<<Bb * 8, 256>>>(nodes);
    k_embed<<<Bb * 16 * 4, 256>>>(Ex);
    k_x1<<<Nn / 2, 256>>>(Wd);
    k_ln1<<<Bb * 32, 256>>>();
    k_ln2<<<Bb, 32>>>();
    k_adp<<<(Bb * Nn) / 32, 128, smem_adp>>>(Wx);
    k_adj<<<Bb * 125, NTH, smem_adj>>>(out);
}